// round 7
// baseline (speedup 1.0000x reference)
#include <cuda_runtime.h>

// PatchEmbedding: x(1,3,384,384) f32, W(768,12), b(768), positions(768,146689)
// out[e,l] = b[e] + positions[e,l] + sum_d patch[d,l] * W[e,d]
// d = c*4 + i*2 + j, l = r*383 + col, patch value = x[c, r+i, col+j]
//
// W/b in __constant__ (uniform LDCU path, 128-bit reads). Two l-streams per
// thread + double-buffered 8-deep prefetch -> 16 pos lines in flight per warp.

#define IMG      384
#define LW       383
#define L_TOTAL  (383 * 383)         // 146689
#define EMB      768
#define PD       12

#define TPB      256
#define LPT      2                   // l and l+TPB per thread
#define L_TILE   (TPB * LPT)         // 512
#define E_TILE   64                  // 768/64 = 12 y-blocks
#define CH       8                   // ee per prefetch chunk
#define NCH      (E_TILE / CH)       // 8

__constant__ float4 cW4[EMB * 3];    // W rows as 3 float4 each (36 KB)
__constant__ float  cB[EMB];         // 3 KB

__device__ __forceinline__ void gather_patch(const float* __restrict__ x,
                                             int l, float* p) {
    const int r   = l / LW;
    const int col = l - r * LW;
    const float* xp = x + r * IMG + col;
    #pragma unroll
    for (int c = 0; c < 3; c++)
        #pragma unroll
        for (int i = 0; i < 2; i++)
            #pragma unroll
            for (int j = 0; j < 2; j++)
                p[c * 4 + i * 2 + j] = xp[c * IMG * IMG + i * IMG + j];
}

__device__ __forceinline__ float dot12(const float* p,
                                       float4 w0, float4 w1, float4 w2) {
    float c0 = p[0] * w0.x;
    float c1 = p[1] * w0.y;
    c0 = fmaf(p[2],  w0.z, c0);  c1 = fmaf(p[3],  w0.w, c1);
    c0 = fmaf(p[4],  w1.x, c0);  c1 = fmaf(p[5],  w1.y, c1);
    c0 = fmaf(p[6],  w1.z, c0);  c1 = fmaf(p[7],  w1.w, c1);
    c0 = fmaf(p[8],  w2.x, c0);  c1 = fmaf(p[9],  w2.y, c1);
    c0 = fmaf(p[10], w2.z, c0);  c1 = fmaf(p[11], w2.w, c1);
    return c0 + c1;
}

__global__ __launch_bounds__(TPB, 4)
void patch_embed_kernel(const float* __restrict__ x,
                        const float* __restrict__ pos,
                        float* __restrict__ out) {
    const int e0    = blockIdx.y * E_TILE;
    const int lbase = blockIdx.x * L_TILE + threadIdx.x;
    const bool full_block = (blockIdx.x + 1) * L_TILE <= L_TOTAL;

    if (full_block) {
        // ---- fast path: no predication ----
        float p[LPT][PD];
        #pragma unroll
        for (int k = 0; k < LPT; k++)
            gather_patch(x, lbase + k * TPB, p[k]);

        const float* __restrict__ posrow = pos + (size_t)e0 * L_TOTAL + lbase;
        float*       __restrict__ outrow = out + (size_t)e0 * L_TOTAL + lbase;

        // Double-buffered prefetch: 16 independent streaming loads in flight.
        float pv[2][CH][LPT];

        #pragma unroll
        for (int j = 0; j < CH; j++)
            #pragma unroll
            for (int k = 0; k < LPT; k++)
                pv[0][j][k] = __ldcs(posrow + (size_t)j * L_TOTAL + k * TPB);

        #pragma unroll
        for (int cc = 0; cc < NCH; cc++) {
            const int cur = cc & 1;

            if (cc + 1 < NCH) {
                const int eb = (cc + 1) * CH;
                #pragma unroll
                for (int j = 0; j < CH; j++)
                    #pragma unroll
                    for (int k = 0; k < LPT; k++)
                        pv[cur ^ 1][j][k] =
                            __ldcs(posrow + (size_t)(eb + j) * L_TOTAL + k * TPB);
            }

            #pragma unroll
            for (int j = 0; j < CH; j++) {
                const int ee = cc * CH + j;
                const float4 w0 = cW4[(e0 + ee) * 3 + 0];
                const float4 w1 = cW4[(e0 + ee) * 3 + 1];
                const float4 w2 = cW4[(e0 + ee) * 3 + 2];
                const float  bb = cB[e0 + ee];
                #pragma unroll
                for (int k = 0; k < LPT; k++) {
                    const float d = dot12(p[k], w0, w1, w2);
                    __stcs(outrow + (size_t)ee * L_TOTAL + k * TPB,
                           (bb + pv[cur][j][k]) + d);
                }
            }
        }
    } else {
        // ---- masked tail path (1 of 287 x-blocks) ----
        float p[LPT][PD];
        bool  valid[LPT];
        #pragma unroll
        for (int k = 0; k < LPT; k++) {
            const int l = lbase + k * TPB;
            valid[k] = (l < L_TOTAL);
            gather_patch(x, valid[k] ? l : 0, p[k]);
        }

        const float* __restrict__ posrow = pos + (size_t)e0 * L_TOTAL + lbase;
        float*       __restrict__ outrow = out + (size_t)e0 * L_TOTAL + lbase;

        for (int ee = 0; ee < E_TILE; ee++) {
            const float4 w0 = cW4[(e0 + ee) * 3 + 0];
            const float4 w1 = cW4[(e0 + ee) * 3 + 1];
            const float4 w2 = cW4[(e0 + ee) * 3 + 2];
            const float  bb = cB[e0 + ee];
            #pragma unroll
            for (int k = 0; k < LPT; k++) {
                if (valid[k]) {
                    const float pvv = __ldcs(posrow + (size_t)ee * L_TOTAL + k * TPB);
                    const float d   = dot12(p[k], w0, w1, w2);
                    __stcs(outrow + (size_t)ee * L_TOTAL + k * TPB,
                           (bb + pvv) + d);
                }
            }
        }
    }
}

extern "C" void kernel_launch(void* const* d_in, const int* in_sizes, int n_in,
                              void* d_out, int out_size) {
    const float* x   = (const float*)d_in[0];
    const float* W   = (const float*)d_in[1];
    const float* b   = (const float*)d_in[2];
    const float* pos = (const float*)d_in[3];
    float* out = (float*)d_out;

    // D2D async copies into the constant bank (graph-capturable memcpy nodes).
    cudaMemcpyToSymbolAsync(cW4, W, EMB * PD * sizeof(float), 0,
                            cudaMemcpyDeviceToDevice);
    cudaMemcpyToSymbolAsync(cB, b, EMB * sizeof(float), 0,
                            cudaMemcpyDeviceToDevice);

    dim3 grid((L_TOTAL + L_TILE - 1) / L_TILE,   // 287
              EMB / E_TILE,                      // 12
              1);
    patch_embed_kernel<<<grid, TPB>>>(x, pos, out);
}

// round 8
// speedup vs baseline: 1.3145x; 1.3145x over previous
#include <cuda_runtime.h>
#include <cstdint>

// PatchEmbedding: x(1,3,384,384) f32, W(768,12), b(768), positions(768,146689)
// out[e,l] = b[e] + positions[e,l] + sum_d patch[d,l] * W[e,d]
// d = c*4 + i*2 + j, l = r*383 + col, patch value = x[c, r+i, col+j]
//
// W/b in __constant__ (uniform LDCU path). pos prefetched with a 3-stage
// cp.async smem pipeline: 24 lines in flight per warp, zero register cost.

#define IMG      384
#define LW       383
#define L_TOTAL  (383 * 383)         // 146689
#define EMB      768
#define PD       12

#define TPB      256
#define E_TILE   64                  // 768/64 = 12 y-blocks
#define CH       8                   // ee per pipeline stage
#define NCH      (E_TILE / CH)       // 8 chunks
#define NSTAGE   3                   // cp.async pipeline depth

__constant__ float4 cW4[EMB * 3];    // W rows as 3 float4 each (36 KB)
__constant__ float  cB[EMB];         // 3 KB

__device__ __forceinline__ void gather_patch(const float* __restrict__ x,
                                             int l, float* p) {
    const int r   = l / LW;
    const int col = l - r * LW;
    const float* xp = x + r * IMG + col;
    #pragma unroll
    for (int c = 0; c < 3; c++)
        #pragma unroll
        for (int i = 0; i < 2; i++)
            #pragma unroll
            for (int j = 0; j < 2; j++)
                p[c * 4 + i * 2 + j] = xp[c * IMG * IMG + i * IMG + j];
}

__device__ __forceinline__ float dot12(const float* p,
                                       float4 w0, float4 w1, float4 w2) {
    float c0 = p[0] * w0.x;
    float c1 = p[1] * w0.y;
    c0 = fmaf(p[2],  w0.z, c0);  c1 = fmaf(p[3],  w0.w, c1);
    c0 = fmaf(p[4],  w1.x, c0);  c1 = fmaf(p[5],  w1.y, c1);
    c0 = fmaf(p[6],  w1.z, c0);  c1 = fmaf(p[7],  w1.w, c1);
    c0 = fmaf(p[8],  w2.x, c0);  c1 = fmaf(p[9],  w2.y, c1);
    c0 = fmaf(p[10], w2.z, c0);  c1 = fmaf(p[11], w2.w, c1);
    return c0 + c1;
}

__device__ __forceinline__ void cp_async4(uint32_t smem_addr,
                                          const float* gmem_ptr) {
    asm volatile("cp.async.ca.shared.global [%0], [%1], 4;"
                 :: "r"(smem_addr), "l"(gmem_ptr));
}

__global__ __launch_bounds__(TPB, 6)   // ~40 regs, 24KB smem -> 48 warps/SM
void patch_embed_kernel(const float* __restrict__ x,
                        const float* __restrict__ pos,
                        float* __restrict__ out) {
    __shared__ float spv[NSTAGE][CH * TPB];   // 3 x 8KB

    const int e0    = blockIdx.y * E_TILE;
    const int lbase = blockIdx.x * TPB + threadIdx.x;
    const bool valid = (lbase < L_TOTAL);

    // Patch gather once (x is L2-hot; reused E_TILE times).
    float p[PD];
    gather_patch(x, valid ? lbase : 0, p);

    const float* __restrict__ posrow = pos + (size_t)e0 * L_TOTAL + lbase;
    float*       __restrict__ outrow = out + (size_t)e0 * L_TOTAL + lbase;

    const uint32_t sbase =
        (uint32_t)__cvta_generic_to_shared(&spv[0][0]) + threadIdx.x * 4u;

    // Prologue: issue the first NSTAGE-1 stages.
    #pragma unroll
    for (int s = 0; s < NSTAGE - 1; s++) {
        if (valid) {
            #pragma unroll
            for (int j = 0; j < CH; j++)
                cp_async4(sbase + (uint32_t)(s * CH + j) * (TPB * 4u),
                          posrow + (size_t)(s * CH + j) * L_TOTAL);
        }
        asm volatile("cp.async.commit_group;");
    }

    #pragma unroll
    for (int cc = 0; cc < NCH; cc++) {
        // Issue stage cc+NSTAGE-1 (or an empty group to keep counts uniform).
        {
            const int sf = cc + NSTAGE - 1;
            if (sf < NCH && valid) {
                const int st = sf % NSTAGE;
                #pragma unroll
                for (int j = 0; j < CH; j++)
                    cp_async4(sbase + (uint32_t)(st * CH + j) * (TPB * 4u),
                              posrow + (size_t)(sf * CH + j) * L_TOTAL);
            }
            asm volatile("cp.async.commit_group;");
        }

        // Wait until stage cc's group is complete (NSTAGE-1 groups may remain
        // pending). Each thread reads only its own copied bytes, so no
        // __syncthreads needed.
        asm volatile("cp.async.wait_group %0;" :: "n"(NSTAGE - 1));

        if (valid) {
            const int st = cc % NSTAGE;
            #pragma unroll
            for (int j = 0; j < CH; j++) {
                const int ee = cc * CH + j;
                const float4 w0 = cW4[(e0 + ee) * 3 + 0];
                const float4 w1 = cW4[(e0 + ee) * 3 + 1];
                const float4 w2 = cW4[(e0 + ee) * 3 + 2];
                const float  bb = cB[e0 + ee];
                const float pvv = spv[st][j * TPB + threadIdx.x];
                const float d   = dot12(p, w0, w1, w2);
                __stcs(outrow + (size_t)ee * L_TOTAL, (bb + pvv) + d);
            }
        }
    }
}

extern "C" void kernel_launch(void* const* d_in, const int* in_sizes, int n_in,
                              void* d_out, int out_size) {
    const float* x   = (const float*)d_in[0];
    const float* W   = (const float*)d_in[1];
    const float* b   = (const float*)d_in[2];
    const float* pos = (const float*)d_in[3];
    float* out = (float*)d_out;

    // D2D async copies into the constant bank (graph-capturable memcpy nodes).
    cudaMemcpyToSymbolAsync(cW4, W, EMB * PD * sizeof(float), 0,
                            cudaMemcpyDeviceToDevice);
    cudaMemcpyToSymbolAsync(cB, b, EMB * sizeof(float), 0,
                            cudaMemcpyDeviceToDevice);

    dim3 grid((L_TOTAL + TPB - 1) / TPB,   // 574
              EMB / E_TILE,                // 12
              1);
    patch_embed_kernel<<<grid, TPB>>>(x, pos, out);
}

// round 9
// speedup vs baseline: 1.5005x; 1.1415x over previous
#include <cuda_runtime.h>
#include <cstdint>

// PatchEmbedding: x(1,3,384,384) f32, W(768,12), b(768), positions(768,146689)
// out[e,l] = b[e] + positions[e,l] + sum_d patch[d,l] * W[e,d]
//
// W/b in __constant__ (uniform const path). pos streamed into smem by a
// single-thread cp.async.bulk + mbarrier pipeline (1 instr per 1KB row),
// so compute warps never issue a long-latency load.

#define IMG      384
#define LW       383
#define L_TOTAL  (383 * 383)         // 146689
#define EMB      768
#define PD       12

#define TPB      256
#define E_TILE   64                  // 768/64 = 12 y-blocks
#define CH       8                   // e-rows per stage
#define NCH      (E_TILE / CH)       // 8 stages of work
#define NSTAGE   3                   // ring depth

// Row copy: 260 floats (1040B, 16B-multiple) starting at src - (e&3) floats,
// so the 16B-alignment requirement holds for every e (L is odd).
#define ROWF     260
#define ROWB     (ROWF * 4)          // 1040
#define STAGEF   (CH * ROWF)         // 2080 floats
#define STAGEB   (CH * ROWB)         // 8320 bytes

__constant__ float4 cW4[EMB * 3];
__constant__ float  cB[EMB];

__device__ __forceinline__ void gather_patch(const float* __restrict__ x,
                                             int l, float* p) {
    const int r   = l / LW;
    const int col = l - r * LW;
    const float* xp = x + r * IMG + col;
    #pragma unroll
    for (int c = 0; c < 3; c++)
        #pragma unroll
        for (int i = 0; i < 2; i++)
            #pragma unroll
            for (int j = 0; j < 2; j++)
                p[c * 4 + i * 2 + j] = xp[c * IMG * IMG + i * IMG + j];
}

__device__ __forceinline__ float dot12(const float* p,
                                       float4 w0, float4 w1, float4 w2) {
    float c0 = p[0] * w0.x;
    float c1 = p[1] * w0.y;
    c0 = fmaf(p[2],  w0.z, c0);  c1 = fmaf(p[3],  w0.w, c1);
    c0 = fmaf(p[4],  w1.x, c0);  c1 = fmaf(p[5],  w1.y, c1);
    c0 = fmaf(p[6],  w1.z, c0);  c1 = fmaf(p[7],  w1.w, c1);
    c0 = fmaf(p[8],  w2.x, c0);  c1 = fmaf(p[9],  w2.y, c1);
    c0 = fmaf(p[10], w2.z, c0);  c1 = fmaf(p[11], w2.w, c1);
    return c0 + c1;
}

__device__ __forceinline__ void mbar_init(uint32_t bar, uint32_t cnt) {
    asm volatile("mbarrier.init.shared.b64 [%0], %1;" :: "r"(bar), "r"(cnt) : "memory");
}
__device__ __forceinline__ void mbar_expect_tx(uint32_t bar, uint32_t bytes) {
    asm volatile("mbarrier.arrive.expect_tx.shared.b64 _, [%0], %1;"
                 :: "r"(bar), "r"(bytes) : "memory");
}
__device__ __forceinline__ void mbar_arrive(uint32_t bar) {
    asm volatile("mbarrier.arrive.shared.b64 _, [%0];" :: "r"(bar) : "memory");
}
__device__ __forceinline__ void mbar_wait(uint32_t bar, uint32_t parity) {
    asm volatile(
        "{\n\t.reg .pred P;\n\t"
        "W%=:\n\t"
        "mbarrier.try_wait.parity.shared.b64 P, [%0], %1, 0x989680;\n\t"
        "@P bra.uni D%=;\n\t"
        "bra.uni W%=;\n\t"
        "D%=:\n\t}"
        :: "r"(bar), "r"(parity) : "memory");
}
__device__ __forceinline__ void bulk_cp(uint32_t dst, const float* src,
                                        uint32_t bar) {
    asm volatile(
        "cp.async.bulk.shared::cta.global.mbarrier::complete_tx::bytes "
        "[%0], [%1], %2, [%3];"
        :: "r"(dst), "l"(src), "r"((uint32_t)ROWB), "r"(bar) : "memory");
}

__global__ __launch_bounds__(TPB, 6)
void patch_embed_kernel(const float* __restrict__ x,
                        const float* __restrict__ pos,
                        float* __restrict__ out) {
    __shared__ __align__(16) float spv[NSTAGE * STAGEF];   // 24,960 B
    __shared__ __align__(8)  unsigned long long mbar[2 * NSTAGE];

    const int e0 = blockIdx.y * E_TILE;
    const int l0 = blockIdx.x * TPB;
    const int lbase = l0 + threadIdx.x;

    if (blockIdx.x == gridDim.x - 1) {
        // ---- tail x-block: exactly 1 valid l (146688); scalar path ----
        if (lbase < L_TOTAL) {
            float p[PD];
            gather_patch(x, lbase, p);
            for (int ee = 0; ee < E_TILE; ee++) {
                const int e = e0 + ee;
                const float4 w0 = cW4[e * 3 + 0];
                const float4 w1 = cW4[e * 3 + 1];
                const float4 w2 = cW4[e * 3 + 2];
                const float pvv = pos[(size_t)e * L_TOTAL + lbase];
                out[(size_t)e * L_TOTAL + lbase] =
                    (cB[e] + pvv) + dot12(p, w0, w1, w2);
            }
        }
        return;
    }

    // ---- full blocks ----
    const uint32_t sbase = (uint32_t)__cvta_generic_to_shared(spv);
    const uint32_t bbase = (uint32_t)__cvta_generic_to_shared(mbar);
    #define FULLB(s)  (bbase + (uint32_t)(s) * 8u)
    #define EMPTYB(s) (bbase + (uint32_t)(NSTAGE + (s)) * 8u)

    if (threadIdx.x == 0) {
        #pragma unroll
        for (int s = 0; s < NSTAGE; s++) {
            mbar_init(FULLB(s), 1);
            mbar_init(EMPTYB(s), TPB);
        }
        asm volatile("fence.proxy.async.shared::cta;" ::: "memory");
    }

    float p[PD];
    gather_patch(x, lbase, p);

    __syncthreads();   // mbarriers visible to all before any use

    const float* __restrict__ posblk = pos + (size_t)e0 * L_TOTAL + l0;
    float*       __restrict__ outrow = out + (size_t)e0 * L_TOTAL + lbase;

    // Prologue: issue stages 0..NSTAGE-2.
    if (threadIdx.x == 0) {
        #pragma unroll
        for (int s = 0; s < NSTAGE - 1; s++) {
            mbar_expect_tx(FULLB(s), STAGEB);
            #pragma unroll
            for (int j = 0; j < CH; j++)
                bulk_cp(sbase + (uint32_t)(s * STAGEB + j * ROWB),
                        posblk + (size_t)(s * CH + j) * L_TOTAL - (j & 3),
                        FULLB(s));
        }
    }

    #pragma unroll
    for (int cc = 0; cc < NCH; cc++) {
        // Producer: issue stage cc+NSTAGE-1 ahead of consuming cc.
        if (threadIdx.x == 0) {
            const int s = cc + NSTAGE - 1;
            if (s < NCH) {
                const int st = s % NSTAGE;
                const int k  = s / NSTAGE;          // fill number of this slot
                if (k > 0)
                    mbar_wait(EMPTYB(st), (uint32_t)((k - 1) & 1));
                mbar_expect_tx(FULLB(st), STAGEB);
                #pragma unroll
                for (int j = 0; j < CH; j++)
                    bulk_cp(sbase + (uint32_t)(st * STAGEB + j * ROWB),
                            posblk + (size_t)(s * CH + j) * L_TOTAL - (j & 3),
                            FULLB(st));
            }
        }

        const int st = cc % NSTAGE;
        mbar_wait(FULLB(st), (uint32_t)((cc / NSTAGE) & 1));

        #pragma unroll
        for (int j = 0; j < CH; j++) {
            const int e = e0 + cc * CH + j;
            const float4 w0 = cW4[e * 3 + 0];
            const float4 w1 = cW4[e * 3 + 1];
            const float4 w2 = cW4[e * 3 + 2];
            const float pvv = spv[st * STAGEF + j * ROWF + (j & 3) + threadIdx.x];
            const float d   = dot12(p, w0, w1, w2);
            __stcs(outrow + (size_t)(cc * CH + j) * L_TOTAL,
                   (cB[e] + pvv) + d);
        }

        mbar_arrive(EMPTYB(st));
    }
}

extern "C" void kernel_launch(void* const* d_in, const int* in_sizes, int n_in,
                              void* d_out, int out_size) {
    const float* x   = (const float*)d_in[0];
    const float* W   = (const float*)d_in[1];
    const float* b   = (const float*)d_in[2];
    const float* pos = (const float*)d_in[3];
    float* out = (float*)d_out;

    cudaMemcpyToSymbolAsync(cW4, W, EMB * PD * sizeof(float), 0,
                            cudaMemcpyDeviceToDevice);
    cudaMemcpyToSymbolAsync(cB, b, EMB * sizeof(float), 0,
                            cudaMemcpyDeviceToDevice);

    dim3 grid((L_TOTAL + TPB - 1) / TPB,   // 574 (last block = tail path)
              EMB / E_TILE,                // 12
              1);
    patch_embed_kernel<<<grid, TPB>>>(x, pos, out);
}